// round 7
// baseline (speedup 1.0000x reference)
#include <cuda_runtime.h>
#include <mma.h>
#include <cstdint>

using namespace nvcuda;

// NOTE (environment pitfall): this harness generates PTX at virtual target
// sm_103 (no 'a' suffix) — ptxas rejects all tcgen05/TMEM instructions.
// The legacy mma.sync (HMMA) path is the usable tensor engine here.

// ---------------- problem constants ----------------
#define BQ 4
#define LQ 8192
#define DQ 1024
#define NHQ 16
#define HDQ 64
#define MT (BQ * LQ)          // 32768 rows
#define ROW_TILES (MT / 128)  // 256
#define COL_TILES (DQ / 256)  // 4  (CTA tile is 128x256 now)
#define NT 64                 // k-stages of 16

// ---------------- device scratch (no allocations allowed) ----------------
__device__ __align__(16) float g_Wv_sumT[NHQ * DQ];  // [head][k]
__device__ __align__(16) float g_bv_sum[NHQ];
__device__ __align__(16) int   g_mask[MT];
__device__ int   g_mask_kind;
__device__ __align__(16) float g_sv[MT * NHQ];
__device__ __align__(16) float g_partial[ROW_TILES * DQ];
__device__ __align__(16) float g_kv_sum[BQ * DQ];

__device__ __forceinline__ float phi_fn(float x) {
    return x > 0.f ? x + 1.f : __expf(x);   // elu(x)+1
}
__device__ __forceinline__ float rtf(float x) { return wmma::__float_to_tf32(x); }

// ---------------- mask dtype detection + normalization ----------------
__global__ void detect_mask_kernel(const unsigned int* m) {
    __shared__ int f_nonbin, f_float;
    if (threadIdx.x == 0) { f_nonbin = 0; f_float = 0; }
    __syncthreads();
    int nb = 0, fl = 0;
    for (int i = threadIdx.x; i < 8192; i += 256) {
        unsigned v = m[i];
        if (v == 0x3F800000u) fl = 1;
        else if (v > 1u) nb = 1;
    }
    if (fl) atomicOr(&f_float, 1);
    if (nb) atomicOr(&f_nonbin, 1);
    __syncthreads();
    if (threadIdx.x == 0) g_mask_kind = f_float ? 2 : (f_nonbin ? 1 : 0);
}

__global__ void normalize_mask_kernel(const void* m) {
    int i = blockIdx.x * 256 + threadIdx.x;
    if (i >= MT) return;
    int kind = g_mask_kind;
    int v;
    if (kind == 2)      v = (((const float*)m)[i] != 0.0f);
    else if (kind == 1) v = (((const unsigned char*)m)[i] != 0);
    else                v = (((const int*)m)[i] != 0);
    g_mask[i] = v;
}

// ---------------- Wv column sums per head (transposed) ----------------
__global__ void wvsum_kernel(const float* __restrict__ Wv,
                             const float* __restrict__ bv) {
    int t = blockIdx.x * 256 + threadIdx.x;
    if (t < DQ * NHQ) {
        int k = t >> 4, n = t & 15;
        const float* p = Wv + (size_t)k * DQ + n * HDQ;
        float s = 0.f;
        #pragma unroll 8
        for (int v = 0; v < HDQ; v++) s += p[v];
        g_Wv_sumT[n * DQ + k] = s;
    }
    if (t < NHQ) {
        const float* p = bv + t * HDQ;
        float s = 0.f;
        #pragma unroll 8
        for (int v = 0; v < HDQ; v++) s += p[v];
        g_bv_sum[t] = s;
    }
}

// ---------------- sv pre-pass (round-5 proven) ----------------
__global__ void __launch_bounds__(256) sv_kernel(const float* __restrict__ X) {
    extern __shared__ __align__(16) float4 sWv[];
    const int tid = threadIdx.x;
    {
        const float4* src = (const float4*)g_Wv_sumT;
        #pragma unroll
        for (int i = 0; i < NHQ * DQ / 4 / 256; i++)
            sWv[i * 256 + tid] = src[i * 256 + tid];
    }
    __syncthreads();

    const int warp = tid >> 5, lane = tid & 31;
    const int row0 = blockIdx.x * 32 + warp * 4;
    const float4* x0 = (const float4*)(X + (size_t)row0 * DQ);
    const float4* x1 = (const float4*)(X + (size_t)(row0 + 1) * DQ);
    const float4* x2 = (const float4*)(X + (size_t)(row0 + 2) * DQ);
    const float4* x3 = (const float4*)(X + (size_t)(row0 + 3) * DQ);

    float acc[4][NHQ];
    #pragma unroll
    for (int p = 0; p < 4; p++)
        #pragma unroll
        for (int h = 0; h < NHQ; h++) acc[p][h] = 0.f;

    for (int c = lane; c < DQ / 4; c += 32) {
        float4 xv0 = x0[c], xv1 = x1[c], xv2 = x2[c], xv3 = x3[c];
        #pragma unroll
        for (int h = 0; h < NHQ; h++) {
            float4 w = sWv[h * (DQ / 4) + c];
            acc[0][h] += xv0.x * w.x + xv0.y * w.y + xv0.z * w.z + xv0.w * w.w;
            acc[1][h] += xv1.x * w.x + xv1.y * w.y + xv1.z * w.z + xv1.w * w.w;
            acc[2][h] += xv2.x * w.x + xv2.y * w.y + xv2.z * w.z + xv2.w * w.w;
            acc[3][h] += xv3.x * w.x + xv3.y * w.y + xv3.z * w.z + xv3.w * w.w;
        }
    }
    #pragma unroll
    for (int off = 16; off; off >>= 1)
        #pragma unroll
        for (int p = 0; p < 4; p++)
            #pragma unroll
            for (int h = 0; h < NHQ; h++)
                acc[p][h] += __shfl_xor_sync(0xffffffffu, acc[p][h], off);
    if (lane < NHQ) {
        float bvs = g_bv_sum[lane];
        #pragma unroll
        for (int p = 0; p < 4; p++) {
            int m = g_mask[row0 + p];
            g_sv[(size_t)(row0 + p) * NHQ + lane] = m ? 0.f : acc[p][lane] + bvs;
        }
    }
}

// ---------------- main GEMM: 128x256 CTA tile, 64x64 warp tiles -------------
#define AS_LD 20
#define BS_LD 260
#define CT_LD 132
#define A_FLOATS (128 * AS_LD)            // 2560
#define STG_F (A_FLOATS + 16 * BS_LD)     // 6720 floats per stage
#define GSMEM_F (128 * CT_LD)             // 16896 floats (> 2*STG_F = 13440)
#define GSMEM_B (GSMEM_F * 4)             // 67584 bytes

template <int MODE>
__global__ void __launch_bounds__(256)
gemm_kernel(const float* __restrict__ X, const float* __restrict__ W,
            const float* __restrict__ bias, float* __restrict__ outp) {
    extern __shared__ __align__(16) float ds[];   // union: stages | Ct
    __shared__ __align__(16) float svred4[128 * 4];
    __shared__ float red2s[256];

    const int tid = threadIdx.x;
    const int bn = blockIdx.x;   // 256-col tile (4 heads)
    const int br = blockIdx.y;   // 128-row tile

    const int wid = tid >> 5;
    const int wm = wid & 1;      // warp rows: wm*64 .. +63
    const int wn = wid >> 1;     // warp cols: wn*64 .. +63

    // A staging: one row per thread, k-half by tid>>7
    const int arow = tid & 127, ak8 = (tid >> 7) * 8;
    const float* Asrc = X + (size_t)(br * 128 + arow) * DQ + ak8;
    const int aoff = arow * AS_LD + ak8;
    // B staging: 4 rows x 4 cols per thread (row-group of 64 threads)
    const int brow0 = (tid >> 6) * 4, bcol = (tid & 63) * 4;
    const float* Bsrc = W + (size_t)brow0 * DQ + bn * 256 + bcol;
    const int boff = A_FLOATS + brow0 * BS_LD + bcol;

    wmma::fragment<wmma::accumulator, 16, 16, 8, float> fc[4][4];
    #pragma unroll
    for (int i = 0; i < 4; i++)
        #pragma unroll
        for (int j = 0; j < 4; j++)
            wmma::fill_fragment(fc[i][j], 0.f);

    // ---- preload stage 0 ----
    {
        float4 a0 = *(const float4*)(Asrc);
        float4 a1 = *(const float4*)(Asrc + 4);
        a0.x = rtf(a0.x); a0.y = rtf(a0.y); a0.z = rtf(a0.z); a0.w = rtf(a0.w);
        a1.x = rtf(a1.x); a1.y = rtf(a1.y); a1.z = rtf(a1.z); a1.w = rtf(a1.w);
        *(float4*)(ds + aoff) = a0;
        *(float4*)(ds + aoff + 4) = a1;
        #pragma unroll
        for (int i = 0; i < 4; i++) {
            float4 b = *(const float4*)(Bsrc + (size_t)i * DQ);
            b.x = rtf(b.x); b.y = rtf(b.y); b.z = rtf(b.z); b.w = rtf(b.w);
            *(float4*)(ds + boff + i * BS_LD) = b;
        }
    }
    __syncthreads();

    for (int t = 0; t < NT; t++) {
        const int buf = t & 1;
        float4 na0, na1, nb[4];
        if (t < NT - 1) {
            const int kt = (t + 1) * 16;
            na0 = *(const float4*)(Asrc + kt);
            na1 = *(const float4*)(Asrc + kt + 4);
            #pragma unroll
            for (int i = 0; i < 4; i++)
                nb[i] = *(const float4*)(Bsrc + (size_t)(kt + i) * DQ);
        }

        // compute on ds[buf]
        const float* As = ds + buf * STG_F;
        const float* Bs = As + A_FLOATS;
        #pragma unroll
        for (int kk = 0; kk < 2; kk++) {
            wmma::fragment<wmma::matrix_a, 16, 16, 8, wmma::precision::tf32, wmma::row_major> fa[4];
            wmma::fragment<wmma::matrix_b, 16, 16, 8, wmma::precision::tf32, wmma::row_major> fb[4];
            #pragma unroll
            for (int i = 0; i < 4; i++)
                wmma::load_matrix_sync(fa[i], &As[(wm * 64 + i * 16) * AS_LD + kk * 8], AS_LD);
            #pragma unroll
            for (int j = 0; j < 4; j++)
                wmma::load_matrix_sync(fb[j], &Bs[(kk * 8) * BS_LD + wn * 64 + j * 16], BS_LD);
            #pragma unroll
            for (int i = 0; i < 4; i++)
                #pragma unroll
                for (int j = 0; j < 4; j++)
                    wmma::mma_sync(fc[i][j], fa[i], fb[j], fc[i][j]);
        }

        if (t < NT - 1) {
            float* dAs = ds + (buf ^ 1) * STG_F;
            na0.x = rtf(na0.x); na0.y = rtf(na0.y); na0.z = rtf(na0.z); na0.w = rtf(na0.w);
            na1.x = rtf(na1.x); na1.y = rtf(na1.y); na1.z = rtf(na1.z); na1.w = rtf(na1.w);
            *(float4*)(dAs + aoff) = na0;
            *(float4*)(dAs + aoff + 4) = na1;
            #pragma unroll
            for (int i = 0; i < 4; i++) {
                float4 b = nb[i];
                b.x = rtf(b.x); b.y = rtf(b.y); b.z = rtf(b.z); b.w = rtf(b.w);
                *(float4*)(dAs + boff + i * BS_LD) = b;
            }
        }
        __syncthreads();
    }

    // ---- epilogue: two 128-col halves through smem Ct ----
    if (MODE == 0) {
        if (tid < 128) {
            // heads 4*bn .. 4*bn+3 for this 256-col tile
            float4 s = *(const float4*)(g_sv + (size_t)(br * 128 + tid) * NHQ + bn * 4);
            *(float4*)(svred4 + tid * 4) = s;
        }
    }

    #pragma unroll
    for (int hh = 0; hh < 2; hh++) {
        __syncthreads();
        if ((wn >> 1) == hh) {
            #pragma unroll
            for (int i = 0; i < 4; i++)
                #pragma unroll
                for (int j = 0; j < 4; j++)
                    wmma::store_matrix_sync(&ds[(wm * 64 + i * 16) * CT_LD + (wn & 1) * 64 + j * 16],
                                            fc[i][j], CT_LD, wmma::mem_row_major);
        }
        __syncthreads();
        const int c = tid & 127, rg = tid >> 7;
        const int gcol = bn * 256 + hh * 128 + c;
        const float bias_c = bias[gcol];
        if (MODE == 0) {
            const int head = (hh << 1) + (c >> 6);   // local head 0..3
            float part = 0.f;
            #pragma unroll 8
            for (int r = rg * 64; r < rg * 64 + 64; r++)
                part += phi_fn(ds[r * CT_LD + c] + bias_c) * svred4[r * 4 + head];
            red2s[tid] = part;
            __syncthreads();
            if (tid < 128)
                g_partial[(size_t)br * DQ + bn * 256 + hh * 128 + tid] =
                    red2s[tid] + red2s[128 + tid];
        } else {
            const float kvs = g_kv_sum[(br >> 6) * DQ + gcol];
            #pragma unroll 8
            for (int r = rg * 64; r < rg * 64 + 64; r++)
                outp[(size_t)(br * 128 + r) * DQ + gcol] =
                    phi_fn(ds[r * CT_LD + c] + bias_c) * kvs;
        }
    }
}

// ---------------- deterministic reduction of per-tile partials ----------------
__global__ void kvreduce_kernel() {
    int t = blockIdx.x * 256 + threadIdx.x;
    if (t >= BQ * DQ) return;
    int b = t >> 10, c = t & 1023;
    const float* p = g_partial + (size_t)(b * 64) * DQ + c;
    float s = 0.f;
    #pragma unroll 8
    for (int j = 0; j < 64; j++) s += p[(size_t)j * DQ];
    g_kv_sum[t] = s;
}

// ---------------- entry point ----------------
extern "C" void kernel_launch(void* const* d_in, const int* in_sizes, int n_in,
                              void* d_out, int out_size) {
    const float* query = (const float*)d_in[0];
    const void*  mask  = d_in[1];
    const float* Wq    = (const float*)d_in[2];
    const float* bq    = (const float*)d_in[3];
    const float* Wk    = (const float*)d_in[4];
    const float* bk    = (const float*)d_in[5];
    const float* Wv    = (const float*)d_in[6];
    const float* bv    = (const float*)d_in[7];
    float* out = (float*)d_out;

    const int sv_smem = NHQ * DQ * 4;   // 64KB
    cudaFuncSetAttribute(sv_kernel, cudaFuncAttributeMaxDynamicSharedMemorySize, sv_smem);
    cudaFuncSetAttribute(gemm_kernel<0>, cudaFuncAttributeMaxDynamicSharedMemorySize, GSMEM_B);
    cudaFuncSetAttribute(gemm_kernel<1>, cudaFuncAttributeMaxDynamicSharedMemorySize, GSMEM_B);

    detect_mask_kernel<<<1, 256>>>((const unsigned int*)mask);
    normalize_mask_kernel<<<MT / 256, 256>>>(mask);
    wvsum_kernel<<<(DQ * NHQ + 255) / 256, 256>>>(Wv, bv);
    sv_kernel<<<MT / 32, 256, sv_smem>>>(query);
    gemm_kernel<0><<<dim3(COL_TILES, ROW_TILES), 256, GSMEM_B>>>(query, Wk, bk, nullptr);
    kvreduce_kernel<<<(BQ * DQ + 255) / 256, 256>>>();
    gemm_kernel<1><<<dim3(COL_TILES, ROW_TILES), 256, GSMEM_B>>>(query, Wq, bq, out);
}

// round 9
// speedup vs baseline: 1.0661x; 1.0661x over previous
#include <cuda_runtime.h>
#include <mma.h>
#include <cstdint>

using namespace nvcuda;

// NOTE (environment pitfalls, confirmed):
//  - Harness PTX targets sm_103 (no 'a'): all tcgen05/TMEM instructions are
//    rejected by ptxas. Legacy mma.sync (HMMA) is the usable tensor engine.
//  - Huge static __device__ globals (128MB) were present in both corrupted
//    rounds; this version keeps scratch ~3MB and converts tf32 in-register.

// ---------------- problem constants ----------------
#define BQ 4
#define LQ 8192
#define DQ 1024
#define NHQ 16
#define HDQ 64
#define MT (BQ * LQ)          // 32768 rows
#define ROW_TILES (MT / 128)  // 256
#define COL_TILES (DQ / 128)  // 8
#define NT 64                 // k-stages of 16

// ---------------- device scratch (no allocations allowed) ----------------
__device__ __align__(16) float g_Wv_sumT[NHQ * DQ];  // [head][k]
__device__ __align__(16) float g_bv_sum[NHQ];
__device__ __align__(16) int   g_mask[MT];
__device__ int   g_mask_kind;
__device__ __align__(16) float g_sv[MT * NHQ];
__device__ __align__(16) float g_partial[ROW_TILES * DQ];
__device__ __align__(16) float g_kv_sum[BQ * DQ];

__device__ __forceinline__ float phi_fn(float x) {
    return x > 0.f ? x + 1.f : __expf(x);   // elu(x)+1
}
__device__ __forceinline__ float rtf(float x) { return wmma::__float_to_tf32(x); }

// ---------------- mask dtype detection + normalization ----------------
__global__ void detect_mask_kernel(const unsigned int* m) {
    __shared__ int f_nonbin, f_float;
    if (threadIdx.x == 0) { f_nonbin = 0; f_float = 0; }
    __syncthreads();
    int nb = 0, fl = 0;
    for (int i = threadIdx.x; i < 8192; i += 256) {
        unsigned v = m[i];
        if (v == 0x3F800000u) fl = 1;
        else if (v > 1u) nb = 1;
    }
    if (fl) atomicOr(&f_float, 1);
    if (nb) atomicOr(&f_nonbin, 1);
    __syncthreads();
    if (threadIdx.x == 0) g_mask_kind = f_float ? 2 : (f_nonbin ? 1 : 0);
}

__global__ void normalize_mask_kernel(const void* m) {
    int i = blockIdx.x * 256 + threadIdx.x;
    if (i >= MT) return;
    int kind = g_mask_kind;
    int v;
    if (kind == 2)      v = (((const float*)m)[i] != 0.0f);
    else if (kind == 1) v = (((const unsigned char*)m)[i] != 0);
    else                v = (((const int*)m)[i] != 0);
    g_mask[i] = v;
}

// ---------------- Wv column sums per head (transposed) ----------------
__global__ void wvsum_kernel(const float* __restrict__ Wv,
                             const float* __restrict__ bv) {
    int t = blockIdx.x * 256 + threadIdx.x;
    if (t < DQ * NHQ) {
        int k = t >> 4, n = t & 15;
        const float* p = Wv + (size_t)k * DQ + n * HDQ;
        float s = 0.f;
        #pragma unroll 8
        for (int v = 0; v < HDQ; v++) s += p[v];
        g_Wv_sumT[n * DQ + k] = s;
    }
    if (t < NHQ) {
        const float* p = bv + t * HDQ;
        float s = 0.f;
        #pragma unroll 8
        for (int v = 0; v < HDQ; v++) s += p[v];
        g_bv_sum[t] = s;
    }
}

// ---------------- sv pre-pass (round-5 proven) ----------------
__global__ void __launch_bounds__(256) sv_kernel(const float* __restrict__ X) {
    extern __shared__ __align__(16) float4 sWv[];
    const int tid = threadIdx.x;
    {
        const float4* src = (const float4*)g_Wv_sumT;
        #pragma unroll
        for (int i = 0; i < NHQ * DQ / 4 / 256; i++)
            sWv[i * 256 + tid] = src[i * 256 + tid];
    }
    __syncthreads();

    const int warp = tid >> 5, lane = tid & 31;
    const int row0 = blockIdx.x * 32 + warp * 4;
    const float4* x0 = (const float4*)(X + (size_t)row0 * DQ);
    const float4* x1 = (const float4*)(X + (size_t)(row0 + 1) * DQ);
    const float4* x2 = (const float4*)(X + (size_t)(row0 + 2) * DQ);
    const float4* x3 = (const float4*)(X + (size_t)(row0 + 3) * DQ);

    float acc[4][NHQ];
    #pragma unroll
    for (int p = 0; p < 4; p++)
        #pragma unroll
        for (int h = 0; h < NHQ; h++) acc[p][h] = 0.f;

    for (int c = lane; c < DQ / 4; c += 32) {
        float4 xv0 = x0[c], xv1 = x1[c], xv2 = x2[c], xv3 = x3[c];
        #pragma unroll
        for (int h = 0; h < NHQ; h++) {
            float4 w = sWv[h * (DQ / 4) + c];
            acc[0][h] += xv0.x * w.x + xv0.y * w.y + xv0.z * w.z + xv0.w * w.w;
            acc[1][h] += xv1.x * w.x + xv1.y * w.y + xv1.z * w.z + xv1.w * w.w;
            acc[2][h] += xv2.x * w.x + xv2.y * w.y + xv2.z * w.z + xv2.w * w.w;
            acc[3][h] += xv3.x * w.x + xv3.y * w.y + xv3.z * w.z + xv3.w * w.w;
        }
    }
    #pragma unroll
    for (int off = 16; off; off >>= 1)
        #pragma unroll
        for (int p = 0; p < 4; p++)
            #pragma unroll
            for (int h = 0; h < NHQ; h++)
                acc[p][h] += __shfl_xor_sync(0xffffffffu, acc[p][h], off);
    if (lane < NHQ) {
        float bvs = g_bv_sum[lane];
        #pragma unroll
        for (int p = 0; p < 4; p++) {
            int m = g_mask[row0 + p];
            g_sv[(size_t)(row0 + p) * NHQ + lane] = m ? 0.f : acc[p][lane] + bvs;
        }
    }
}

// ---------------- main GEMM: 128x128 tile, cp.async pipeline, tf32 wmma ----
// Raw fp32 goes through cp.async -> smem -> fragments; RN-tf32 conversion is
// applied IN-REGISTER on fragment elements (deterministic, same numerics as
// pre-rounding, no scratch copies of X/W needed).
#define STAGES 4
#define AS_LD 20
#define BS_LD 132
#define A_STG (128 * AS_LD)                   // 2560 floats per A stage
#define B_STG (16 * BS_LD)                    // 2112 floats per B stage
#define B_BASE (STAGES * A_STG)               // 10240
#define SMEM_FLOATS (B_BASE + STAGES * B_STG) // 18688 floats = 74752 B
#define CT_LD 68

__device__ __forceinline__ void cp16(uint32_t dst, const float* src) {
    asm volatile("cp.async.cg.shared.global [%0], [%1], 16;" :: "r"(dst), "l"(src));
}
__device__ __forceinline__ void cp_commit() {
    asm volatile("cp.async.commit_group;");
}
__device__ __forceinline__ void cp_wait2() {
    asm volatile("cp.async.wait_group 2;");
}

template <int MODE>
__global__ void __launch_bounds__(256, 2)
gemm_kernel(const float* __restrict__ X, const float* __restrict__ W,
            const float* __restrict__ bias, float* __restrict__ outp) {
    extern __shared__ __align__(16) float ds[];
    __shared__ float svred[256];
    __shared__ float red2[256];

    const int tid = threadIdx.x;
    const int bn = blockIdx.x;   // column tile (128 cols = 2 heads)
    const int br = blockIdx.y;   // row tile

    const float* Ab = X + (size_t)br * 128 * DQ;
    const float* Bb = W + bn * 128;

    // cp.async mapping: 4 x 16B per thread per stage
    const int ar  = tid >> 2, akc = (tid & 3) * 4;   // A rows {ar, ar+64}
    const int brr = tid >> 5, bc  = (tid & 31) * 4;  // B rows {brr, brr+8}
    const float* srcA0 = Ab + (size_t)ar * DQ + akc;
    const float* srcA1 = srcA0 + (size_t)64 * DQ;
    const float* srcB0 = Bb + (size_t)brr * DQ + bc;
    const float* srcB1 = srcB0 + (size_t)8 * DQ;

    uint32_t smem_base = (uint32_t)__cvta_generic_to_shared(ds);
    uint32_t dA0 = smem_base + (uint32_t)(ar * AS_LD + akc) * 4u;
    uint32_t dA1 = dA0 + 64u * AS_LD * 4u;
    uint32_t dB0 = smem_base + (uint32_t)(B_BASE + brr * BS_LD + bc) * 4u;
    uint32_t dB1 = dB0 + 8u * BS_LD * 4u;

    #define ISSUE_STAGE(slot, kt) do {                                          \
        cp16(dA0 + (uint32_t)(slot) * (A_STG * 4u), srcA0 + (kt));              \
        cp16(dA1 + (uint32_t)(slot) * (A_STG * 4u), srcA1 + (kt));              \
        cp16(dB0 + (uint32_t)(slot) * (B_STG * 4u), srcB0 + (size_t)(kt) * DQ); \
        cp16(dB1 + (uint32_t)(slot) * (B_STG * 4u), srcB1 + (size_t)(kt) * DQ); \
        cp_commit(); } while (0)

    ISSUE_STAGE(0, 0);
    ISSUE_STAGE(1, 16);
    ISSUE_STAGE(2, 32);

    const int wid = tid >> 5;
    const int wm = wid & 3;    // warp rows wm*32..+31
    const int wn = wid >> 2;   // warp cols wn*64..+63

    wmma::fragment<wmma::accumulator, 16, 16, 8, float> fc[2][4];
    #pragma unroll
    for (int i = 0; i < 2; i++)
        #pragma unroll
        for (int j = 0; j < 4; j++)
            wmma::fill_fragment(fc[i][j], 0.f);

    for (int t = 0; t < NT; t++) {
        cp_wait2();
        __syncthreads();
        if (t + 3 < NT) {
            ISSUE_STAGE((t + 3) & 3, (t + 3) * 16);
        } else {
            cp_commit();   // empty group keeps wait_group accounting uniform
        }

        const float* As = ds + (t & 3) * A_STG;
        const float* Bs = ds + B_BASE + (t & 3) * B_STG;
        #pragma unroll
        for (int kk = 0; kk < 2; kk++) {
            wmma::fragment<wmma::matrix_a, 16, 16, 8, wmma::precision::tf32, wmma::row_major> fa[2];
            wmma::fragment<wmma::matrix_b, 16, 16, 8, wmma::precision::tf32, wmma::row_major> fb[4];
            #pragma unroll
            for (int i = 0; i < 2; i++) {
                wmma::load_matrix_sync(fa[i], &As[(wm * 32 + i * 16) * AS_LD + kk * 8], AS_LD);
                #pragma unroll
                for (int e = 0; e < fa[i].num_elements; e++)
                    fa[i].x[e] = rtf(fa[i].x[e]);      // RN tf32 in-register
            }
            #pragma unroll
            for (int j = 0; j < 4; j++) {
                wmma::load_matrix_sync(fb[j], &Bs[(kk * 8) * BS_LD + wn * 64 + j * 16], BS_LD);
                #pragma unroll
                for (int e = 0; e < fb[j].num_elements; e++)
                    fb[j].x[e] = rtf(fb[j].x[e]);
            }
            #pragma unroll
            for (int i = 0; i < 2; i++)
                #pragma unroll
                for (int j = 0; j < 4; j++)
                    wmma::mma_sync(fc[i][j], fa[i], fb[j], fc[i][j]);
        }
        __syncthreads();
    }
    __syncthreads();

    if (MODE == 0) {
        if (tid < 128) {
            float2 s = *(const float2*)(g_sv + (size_t)(br * 128 + tid) * NHQ + bn * 2);
            svred[tid * 2 + 0] = s.x;
            svred[tid * 2 + 1] = s.y;
        }
        #pragma unroll
        for (int hh = 0; hh < 2; hh++) {
            __syncthreads();
            if (wn == hh) {
                #pragma unroll
                for (int i = 0; i < 2; i++)
                    #pragma unroll
                    for (int j = 0; j < 4; j++)
                        wmma::store_matrix_sync(&ds[(wm * 32 + i * 16) * CT_LD + j * 16],
                                                fc[i][j], CT_LD, wmma::mem_row_major);
            }
            __syncthreads();
            int c = tid & 63, rg = tid >> 6;
            float bias_c = bias[bn * 128 + hh * 64 + c];
            float part = 0.f;
            #pragma unroll 8
            for (int r = rg; r < 128; r += 4) {
                float x = ds[r * CT_LD + c] + bias_c;
                part += phi_fn(x) * svred[r * 2 + hh];
            }
            red2[rg * 64 + c] = part;
            __syncthreads();
            if (tid < 64) {
                float tot = red2[tid] + red2[64 + tid] + red2[128 + tid] + red2[192 + tid];
                g_partial[(size_t)br * DQ + bn * 128 + hh * 64 + tid] = tot;
            }
        }
    } else {
        int b = br >> 6;
        #pragma unroll
        for (int hh = 0; hh < 2; hh++) {
            __syncthreads();
            if (wn == hh) {
                #pragma unroll
                for (int i = 0; i < 2; i++)
                    #pragma unroll
                    for (int j = 0; j < 4; j++)
                        wmma::store_matrix_sync(&ds[(wm * 32 + i * 16) * CT_LD + j * 16],
                                                fc[i][j], CT_LD, wmma::mem_row_major);
            }
            __syncthreads();
            int c = tid & 63, rg = tid >> 6;
            int gcol = bn * 128 + hh * 64 + c;
            float bias_c = bias[gcol];
            float kvs = g_kv_sum[b * DQ + gcol];
            #pragma unroll 8
            for (int r = rg; r < 128; r += 4) {
                float x = ds[r * CT_LD + c] + bias_c;
                outp[(size_t)(br * 128 + r) * DQ + gcol] = phi_fn(x) * kvs;
            }
        }
    }
    #undef ISSUE_STAGE
}

// ---------------- deterministic reduction of per-tile partials ----------------
__global__ void kvreduce_kernel() {
    int t = blockIdx.x * 256 + threadIdx.x;
    if (t >= BQ * DQ) return;
    int b = t >> 10, c = t & 1023;
    const float* p = g_partial + (size_t)(b * 64) * DQ + c;
    float s = 0.f;
    #pragma unroll 8
    for (int j = 0; j < 64; j++) s += p[(size_t)j * DQ];
    g_kv_sum[t] = s;
}

// ---------------- entry point ----------------
extern "C" void kernel_launch(void* const* d_in, const int* in_sizes, int n_in,
                              void* d_out, int out_size) {
    const float* query = (const float*)d_in[0];
    const void*  mask  = d_in[1];
    const float* Wq    = (const float*)d_in[2];
    const float* bq    = (const float*)d_in[3];
    const float* Wk    = (const float*)d_in[4];
    const float* bk    = (const float*)d_in[5];
    const float* Wv    = (const float*)d_in[6];
    const float* bv    = (const float*)d_in[7];
    float* out = (float*)d_out;

    const int sv_smem = NHQ * DQ * 4;        // 64KB
    const int gemm_smem = SMEM_FLOATS * 4;   // 74752B
    cudaFuncSetAttribute(sv_kernel, cudaFuncAttributeMaxDynamicSharedMemorySize, sv_smem);
    cudaFuncSetAttribute(gemm_kernel<0>, cudaFuncAttributeMaxDynamicSharedMemorySize, gemm_smem);
    cudaFuncSetAttribute(gemm_kernel<1>, cudaFuncAttributeMaxDynamicSharedMemorySize, gemm_smem);

    detect_mask_kernel<<<1, 256>>>((const unsigned int*)mask);
    normalize_mask_kernel<<<MT / 256, 256>>>(mask);
    wvsum_kernel<<<(DQ * NHQ + 255) / 256, 256>>>(Wv, bv);
    sv_kernel<<<MT / 32, 256, sv_smem>>>(query);
    gemm_kernel<0><<<dim3(COL_TILES, ROW_TILES), 256, gemm_smem>>>(query, Wk, bk, nullptr);
    kvreduce_kernel<<<(BQ * DQ + 255) / 256, 256>>>();
    gemm_kernel<1><<<dim3(COL_TILES, ROW_TILES), 256, gemm_smem>>>(query, Wq, bq, out);
}